// round 3
// baseline (speedup 1.0000x reference)
#include <cuda_runtime.h>
#include <cuda_bf16.h>

#define BB      8192
#define FF      2048
#define NRULES  512
#define GG      16
#define NPAIR   136          // upper triangle incl. diagonal of 16x16
#define NSTAT   152          // 16 sums + 136 pair-products
#define CHUNKS  8
#define ROWS_PER_CHUNK (BB / CHUNKS)   // 1024
#define EPSV    1e-5f

// Scratch (device globals: allocation-free per harness rules)
__device__ float g_stats[NRULES][CHUNKS][NSTAT];   // ~2.5 MB partial moments
__device__ __align__(16) float g_wF[FF];           // folded GEMV weights
__device__ float g_c0;                             // folded constant

// ---------------------------------------------------------------------------
// Kernel Z: zero the scatter targets every launch (graph replays reuse them)
// ---------------------------------------------------------------------------
__global__ void zero_kernel(const float* __restrict__ fc2_b) {
    int t = blockIdx.x * blockDim.x + threadIdx.x;
    if (t < FF) g_wF[t] = 0.0f;
    if (t == 0) g_c0 = fc2_b[0];
}

// ---------------------------------------------------------------------------
// Kernel A: per-rule first/second moments of the gathered columns.
// grid = (NRULES, CHUNKS), block = 32 (one warp). Each lane strides rows,
// holding 152 fp32 accumulators in registers. x (64MB) is L2-resident.
// ---------------------------------------------------------------------------
__global__ __launch_bounds__(32) void stats_kernel(const float* __restrict__ x,
                                                   const int* __restrict__ idx) {
    const int n     = blockIdx.x;
    const int chunk = blockIdx.y;
    const int lane  = threadIdx.x;

    int col[GG];
#pragma unroll
    for (int j = 0; j < GG; j++) col[j] = idx[n * GG + j];   // uniform per block

    float s1[GG];
    float s2[NPAIR];
#pragma unroll
    for (int j = 0; j < GG; j++) s1[j] = 0.0f;
#pragma unroll
    for (int p = 0; p < NPAIR; p++) s2[p] = 0.0f;

    const int row0 = chunk * ROWS_PER_CHUNK;
    for (int r = lane; r < ROWS_PER_CHUNK; r += 32) {
        const float* xr = x + (size_t)(row0 + r) * FF;
        float g[GG];
#pragma unroll
        for (int j = 0; j < GG; j++) g[j] = __ldg(xr + col[j]);
#pragma unroll
        for (int j = 0; j < GG; j++) s1[j] += g[j];
        int p = 0;
#pragma unroll
        for (int j = 0; j < GG; j++) {
#pragma unroll
            for (int k = j; k < GG; k++) { s2[p] = fmaf(g[j], g[k], s2[p]); p++; }
        }
    }

    // warp tree-reduce each of the 152 quantities; distribute stores over lanes
    float* dst = g_stats[n][chunk];
#pragma unroll
    for (int q = 0; q < NSTAT; q++) {
        float v = (q < GG) ? s1[q] : s2[q - GG];
#pragma unroll
        for (int o = 16; o > 0; o >>= 1) v += __shfl_xor_sync(0xffffffffu, v, o);
        if (lane == (q & 31)) dst[q] = v;
    }
}

// ---------------------------------------------------------------------------
// Kernel B: fold BN1 -> W2 -> BN2 -> fc2 analytically into gamma, scatter
// into wF. One thread per rule. Shifts (b1, bn1_b, b2) cancel exactly under BN.
// ---------------------------------------------------------------------------
__global__ void fold_kernel(const int* __restrict__ idx,
                            const float* __restrict__ W1,
                            const float* __restrict__ bn1_w,
                            const float* __restrict__ W2,
                            const float* __restrict__ fc2_w) {
    int n = blockIdx.x * blockDim.x + threadIdx.x;
    if (n >= NRULES) return;

    float s[NSTAT];
#pragma unroll
    for (int q = 0; q < NSTAT; q++) {
        float acc = 0.0f;
        for (int c = 0; c < CHUNKS; c++) acc += g_stats[n][c][q];
        s[q] = acc;
    }
    const float invB = 1.0f / (float)BB;

    float mu[GG];
#pragma unroll
    for (int j = 0; j < GG; j++) mu[j] = s[j] * invB;

    float C[GG][GG];
    {
        int p = 0;
        for (int j = 0; j < GG; j++)
            for (int k = j; k < GG; k++) {
                float c = s[GG + p] * invB - mu[j] * mu[k];
                C[j][k] = c; C[k][j] = c;
                p++;
            }
    }

    float alpha[GG];
#pragma unroll
    for (int a = 0; a < GG; a++) alpha[a] = 0.0f;

    for (int j = 0; j < GG; j++) {
        const float* wr = W1 + ((size_t)n * GG + j) * GG;
        float w[GG];
#pragma unroll
        for (int a = 0; a < GG; a++) w[a] = wr[a];
        // var_h = w^T C w
        float varh = 0.0f;
        for (int a = 0; a < GG; a++) {
            float t = 0.0f;
            for (int b = 0; b < GG; b++) t = fmaf(w[b], C[a][b], t);
            varh = fmaf(w[a], t, varh);
        }
        float aj  = bn1_w[n * GG + j] * rsqrtf(varh + EPSV);
        float caj = W2[n * GG + j] * aj;
#pragma unroll
        for (int a = 0; a < GG; a++) alpha[a] = fmaf(caj, w[a], alpha[a]);
    }

    float varo = 0.0f, muoa = 0.0f;
    for (int a = 0; a < GG; a++) {
        float t = 0.0f;
        for (int b = 0; b < GG; b++) t = fmaf(alpha[b], C[a][b], t);
        varo = fmaf(alpha[a], t, varo);
        muoa = fmaf(alpha[a], mu[a], muoa);
    }
    float sc = fc2_w[n] * rsqrtf(varo + EPSV);

    for (int j = 0; j < GG; j++)
        atomicAdd(&g_wF[idx[n * GG + j]], sc * alpha[j]);
    atomicAdd(&g_c0, -sc * muoa);
}

// ---------------------------------------------------------------------------
// Kernel C: out[b] = x[b,:] . wF + c0   (8192x2048 GEMV, x L2-resident)
// warp per row, float4 loads.
// ---------------------------------------------------------------------------
__global__ __launch_bounds__(256) void gemv_kernel(const float* __restrict__ x,
                                                   float* __restrict__ out) {
    const int warp = threadIdx.x >> 5;
    const int lane = threadIdx.x & 31;
    const int row  = blockIdx.x * 8 + warp;

    const float4* xr = reinterpret_cast<const float4*>(x + (size_t)row * FF);
    const float4* wv = reinterpret_cast<const float4*>(g_wF);

    float acc = 0.0f;
#pragma unroll
    for (int i = 0; i < 16; i++) {
        float4 a = __ldg(xr + lane + 32 * i);
        float4 w = wv[lane + 32 * i];
        acc = fmaf(a.x, w.x, acc);
        acc = fmaf(a.y, w.y, acc);
        acc = fmaf(a.z, w.z, acc);
        acc = fmaf(a.w, w.w, acc);
    }
#pragma unroll
    for (int o = 16; o > 0; o >>= 1) acc += __shfl_xor_sync(0xffffffffu, acc, o);
    if (lane == 0) out[row] = acc + g_c0;
}

// ---------------------------------------------------------------------------
extern "C" void kernel_launch(void* const* d_in, const int* in_sizes, int n_in,
                              void* d_out, int out_size) {
    const float* x     = (const float*)d_in[0];
    const int*   idx   = (const int*)  d_in[1];
    const float* W1    = (const float*)d_in[2];
    // d_in[3] = b1, d_in[5] = bn1_b, d_in[7] = b2 : cancel exactly under BN
    const float* bn1_w = (const float*)d_in[4];
    const float* W2    = (const float*)d_in[6];
    const float* fc2_w = (const float*)d_in[8];
    const float* fc2_b = (const float*)d_in[9];
    float* out = (float*)d_out;

    zero_kernel<<<(FF + 255) / 256, 256>>>(fc2_b);

    dim3 sgrid(NRULES, CHUNKS);
    stats_kernel<<<sgrid, 32>>>(x, idx);

    fold_kernel<<<(NRULES + 127) / 128, 128>>>(idx, W1, bn1_w, W2, fc2_w);

    gemv_kernel<<<BB / 8, 256>>>(x, out);
}

// round 4
// speedup vs baseline: 1.5069x; 1.5069x over previous
#include <cuda_runtime.h>
#include <cuda_bf16.h>

#define BB      8192
#define FF      2048
#define NRULES  512
#define GG      16
#define NPAIR   136          // upper triangle incl. diagonal of 16x16
#define NSTAT   152          // 16 sums + 136 pair-products
#define CHUNKS  8
#define ROWS_PER_CHUNK (BB / CHUNKS)   // 1024
#define EPSV    1e-5f

// Scratch (device globals: allocation-free per harness rules)
__device__ float g_xT[(size_t)FF * BB];            // 64MB transposed x
__device__ float g_stats[NRULES][CHUNKS][NSTAT];   // ~2.5 MB partial moments
__device__ __align__(16) float g_wF[FF];           // folded GEMV weights
__device__ float g_c0;                             // folded constant

// ---------------------------------------------------------------------------
// Kernel Z: zero the scatter targets every launch (graph replays reuse them)
// ---------------------------------------------------------------------------
__global__ void zero_kernel(const float* __restrict__ fc2_b) {
    int t = blockIdx.x * blockDim.x + threadIdx.x;
    if (t < FF) g_wF[t] = 0.0f;
    if (t == 0) g_c0 = fc2_b[0];
}

// ---------------------------------------------------------------------------
// Kernel T: tiled transpose x(B,F) -> g_xT(F,B). 32x32 tiles, 256 threads.
// Both global accesses fully coalesced; +1 padding kills bank conflicts.
// ---------------------------------------------------------------------------
__global__ __launch_bounds__(256) void transpose_kernel(const float* __restrict__ x) {
    __shared__ float t[32][33];
    const int tx = threadIdx.x & 31;
    const int ty = threadIdx.x >> 5;          // 0..7
    const int col0 = blockIdx.x * 32;         // F dimension
    const int row0 = blockIdx.y * 32;         // B dimension
#pragma unroll
    for (int i = 0; i < 32; i += 8)
        t[ty + i][tx] = x[(size_t)(row0 + ty + i) * FF + col0 + tx];
    __syncthreads();
#pragma unroll
    for (int i = 0; i < 32; i += 8)
        g_xT[(size_t)(col0 + ty + i) * BB + row0 + tx] = t[tx][ty + i];
}

// ---------------------------------------------------------------------------
// Kernel A: per-rule first/second moments, reading the TRANSPOSED x.
// grid = (NRULES, CHUNKS/4), block = 128 (4 warps, one chunk each).
// Lane loads float2 = 2 consecutive rows of column col[j] -> every warp-load
// is one 256B coalesced access (vs 32 scattered lines before).
// ---------------------------------------------------------------------------
__global__ __launch_bounds__(128) void stats_kernel(const int* __restrict__ idx) {
    const int n     = blockIdx.x;
    const int chunk = blockIdx.y * 4 + (threadIdx.x >> 5);
    const int lane  = threadIdx.x & 31;

    const float* colp[GG];
#pragma unroll
    for (int j = 0; j < GG; j++) {
        int c = idx[n * GG + j];                       // uniform per block
        colp[j] = g_xT + (size_t)c * BB + chunk * ROWS_PER_CHUNK;
    }

    float s1[GG];
    float s2[NPAIR];
#pragma unroll
    for (int j = 0; j < GG; j++) s1[j] = 0.0f;
#pragma unroll
    for (int p = 0; p < NPAIR; p++) s2[p] = 0.0f;

#pragma unroll 1
    for (int it = 0; it < ROWS_PER_CHUNK / 64; it++) {   // 16 iterations
        const int r = it * 64 + lane * 2;                // 2 rows per lane
        float2 g2[GG];
#pragma unroll
        for (int j = 0; j < GG; j++)
            g2[j] = *reinterpret_cast<const float2*>(colp[j] + r);
#pragma unroll
        for (int h = 0; h < 2; h++) {
            float g[GG];
#pragma unroll
            for (int j = 0; j < GG; j++) g[j] = h ? g2[j].y : g2[j].x;
#pragma unroll
            for (int j = 0; j < GG; j++) s1[j] += g[j];
            int p = 0;
#pragma unroll
            for (int j = 0; j < GG; j++) {
#pragma unroll
                for (int k = j; k < GG; k++) { s2[p] = fmaf(g[j], g[k], s2[p]); p++; }
            }
        }
    }

    // warp tree-reduce each of the 152 quantities; distribute stores over lanes
    float* dst = g_stats[n][chunk];
#pragma unroll
    for (int q = 0; q < NSTAT; q++) {
        float v = (q < GG) ? s1[q] : s2[q - GG];
#pragma unroll
        for (int o = 16; o > 0; o >>= 1) v += __shfl_xor_sync(0xffffffffu, v, o);
        if (lane == (q & 31)) dst[q] = v;
    }
}

// ---------------------------------------------------------------------------
// Kernel B: fold BN1 -> W2 -> BN2 -> fc2 analytically into gamma, scatter
// into wF. One thread per rule. Shifts (b1, bn1_b, b2) cancel exactly under BN.
// ---------------------------------------------------------------------------
__global__ void fold_kernel(const int* __restrict__ idx,
                            const float* __restrict__ W1,
                            const float* __restrict__ bn1_w,
                            const float* __restrict__ W2,
                            const float* __restrict__ fc2_w) {
    int n = blockIdx.x * blockDim.x + threadIdx.x;
    if (n >= NRULES) return;

    float s[NSTAT];
#pragma unroll
    for (int q = 0; q < NSTAT; q++) {
        float acc = 0.0f;
        for (int c = 0; c < CHUNKS; c++) acc += g_stats[n][c][q];
        s[q] = acc;
    }
    const float invB = 1.0f / (float)BB;

    float mu[GG];
#pragma unroll
    for (int j = 0; j < GG; j++) mu[j] = s[j] * invB;

    float C[GG][GG];
    {
        int p = 0;
        for (int j = 0; j < GG; j++)
            for (int k = j; k < GG; k++) {
                float c = s[GG + p] * invB - mu[j] * mu[k];
                C[j][k] = c; C[k][j] = c;
                p++;
            }
    }

    float alpha[GG];
#pragma unroll
    for (int a = 0; a < GG; a++) alpha[a] = 0.0f;

    for (int j = 0; j < GG; j++) {
        const float* wr = W1 + ((size_t)n * GG + j) * GG;
        float w[GG];
#pragma unroll
        for (int a = 0; a < GG; a++) w[a] = wr[a];
        // var_h = w^T C w
        float varh = 0.0f;
        for (int a = 0; a < GG; a++) {
            float t = 0.0f;
            for (int b = 0; b < GG; b++) t = fmaf(w[b], C[a][b], t);
            varh = fmaf(w[a], t, varh);
        }
        float aj  = bn1_w[n * GG + j] * rsqrtf(varh + EPSV);
        float caj = W2[n * GG + j] * aj;
#pragma unroll
        for (int a = 0; a < GG; a++) alpha[a] = fmaf(caj, w[a], alpha[a]);
    }

    float varo = 0.0f, muoa = 0.0f;
    for (int a = 0; a < GG; a++) {
        float t = 0.0f;
        for (int b = 0; b < GG; b++) t = fmaf(alpha[b], C[a][b], t);
        varo = fmaf(alpha[a], t, varo);
        muoa = fmaf(alpha[a], mu[a], muoa);
    }
    float sc = fc2_w[n] * rsqrtf(varo + EPSV);

    for (int j = 0; j < GG; j++)
        atomicAdd(&g_wF[idx[n * GG + j]], sc * alpha[j]);
    atomicAdd(&g_c0, -sc * muoa);
}

// ---------------------------------------------------------------------------
// Kernel C: out[b] = x[b,:] . wF + c0   (8192x2048 GEMV)
// warp per row, float4 loads.
// ---------------------------------------------------------------------------
__global__ __launch_bounds__(256) void gemv_kernel(const float* __restrict__ x,
                                                   float* __restrict__ out) {
    const int warp = threadIdx.x >> 5;
    const int lane = threadIdx.x & 31;
    const int row  = blockIdx.x * 8 + warp;

    const float4* xr = reinterpret_cast<const float4*>(x + (size_t)row * FF);
    const float4* wv = reinterpret_cast<const float4*>(g_wF);

    float acc = 0.0f;
#pragma unroll
    for (int i = 0; i < 16; i++) {
        float4 a = __ldg(xr + lane + 32 * i);
        float4 w = wv[lane + 32 * i];
        acc = fmaf(a.x, w.x, acc);
        acc = fmaf(a.y, w.y, acc);
        acc = fmaf(a.z, w.z, acc);
        acc = fmaf(a.w, w.w, acc);
    }
#pragma unroll
    for (int o = 16; o > 0; o >>= 1) acc += __shfl_xor_sync(0xffffffffu, acc, o);
    if (lane == 0) out[row] = acc + g_c0;
}

// ---------------------------------------------------------------------------
extern "C" void kernel_launch(void* const* d_in, const int* in_sizes, int n_in,
                              void* d_out, int out_size) {
    const float* x     = (const float*)d_in[0];
    const int*   idx   = (const int*)  d_in[1];
    const float* W1    = (const float*)d_in[2];
    // d_in[3] = b1, d_in[5] = bn1_b, d_in[7] = b2 : cancel exactly under BN
    const float* bn1_w = (const float*)d_in[4];
    const float* W2    = (const float*)d_in[6];
    const float* fc2_w = (const float*)d_in[8];
    const float* fc2_b = (const float*)d_in[9];
    float* out = (float*)d_out;

    zero_kernel<<<(FF + 255) / 256, 256>>>(fc2_b);

    dim3 tgrid(FF / 32, BB / 32);
    transpose_kernel<<<tgrid, 256>>>(x);

    dim3 sgrid(NRULES, CHUNKS / 4);
    stats_kernel<<<sgrid, 128>>>(idx);

    fold_kernel<<<(NRULES + 127) / 128, 128>>>(idx, W1, bn1_w, W2, fc2_w);

    gemv_kernel<<<BB / 8, 256>>>(x, out);
}

// round 5
// speedup vs baseline: 2.5840x; 1.7148x over previous
#include <cuda_runtime.h>
#include <cuda_bf16.h>

#define BB      8192
#define FF      2048
#define NRULES  512
#define GG      16
#define NPAIR   136          // upper triangle incl. diagonal of 16x16
#define NSTAT   152          // 16 sums + 136 pair-products
#define CHUNKS  8
#define ROWS_PER_CHUNK (BB / CHUNKS)   // 1024
#define EPSV    1e-5f
#define FULLMASK 0xffffffffu

// Scratch (device globals: allocation-free per harness rules)
__device__ float g_xT[(size_t)FF * BB];            // 64MB transposed x
__device__ float g_stats[NRULES][CHUNKS][NSTAT];   // ~2.5 MB partial moments
__device__ __align__(16) float g_wF[FF];           // folded GEMV weights
__device__ float g_c0;                             // folded constant

// ---------------------------------------------------------------------------
// Kernel Z: zero the scatter targets every launch (graph replays reuse them)
// ---------------------------------------------------------------------------
__global__ void zero_kernel(const float* __restrict__ fc2_b) {
    int t = blockIdx.x * blockDim.x + threadIdx.x;
    if (t < FF) g_wF[t] = 0.0f;
    if (t == 0) g_c0 = fc2_b[0];
}

// ---------------------------------------------------------------------------
// Kernel T: tiled transpose x(B,F) -> g_xT(F,B). 32x32 tiles, 256 threads.
// ---------------------------------------------------------------------------
__global__ __launch_bounds__(256) void transpose_kernel(const float* __restrict__ x) {
    __shared__ float t[32][33];
    const int tx = threadIdx.x & 31;
    const int ty = threadIdx.x >> 5;          // 0..7
    const int col0 = blockIdx.x * 32;         // F dimension
    const int row0 = blockIdx.y * 32;         // B dimension
#pragma unroll
    for (int i = 0; i < 32; i += 8)
        t[ty + i][tx] = x[(size_t)(row0 + ty + i) * FF + col0 + tx];
    __syncthreads();
#pragma unroll
    for (int i = 0; i < 32; i += 8)
        g_xT[(size_t)(col0 + ty + i) * BB + row0 + tx] = t[tx][ty + i];
}

// ---------------------------------------------------------------------------
// Kernel A: per-rule first/second moments from the TRANSPOSED x.
// grid = (NRULES, CHUNKS/4), block = 128 (4 warps, one chunk each).
// ---------------------------------------------------------------------------
__global__ __launch_bounds__(128) void stats_kernel(const int* __restrict__ idx) {
    const int n     = blockIdx.x;
    const int chunk = blockIdx.y * 4 + (threadIdx.x >> 5);
    const int lane  = threadIdx.x & 31;

    const float* colp[GG];
#pragma unroll
    for (int j = 0; j < GG; j++) {
        int c = idx[n * GG + j];                       // uniform per block
        colp[j] = g_xT + (size_t)c * BB + chunk * ROWS_PER_CHUNK;
    }

    float s1[GG];
    float s2[NPAIR];
#pragma unroll
    for (int j = 0; j < GG; j++) s1[j] = 0.0f;
#pragma unroll
    for (int p = 0; p < NPAIR; p++) s2[p] = 0.0f;

#pragma unroll 1
    for (int it = 0; it < ROWS_PER_CHUNK / 64; it++) {   // 16 iterations
        const int r = it * 64 + lane * 2;                // 2 rows per lane
        float2 g2[GG];
#pragma unroll
        for (int j = 0; j < GG; j++)
            g2[j] = *reinterpret_cast<const float2*>(colp[j] + r);
#pragma unroll
        for (int h = 0; h < 2; h++) {
            float g[GG];
#pragma unroll
            for (int j = 0; j < GG; j++) g[j] = h ? g2[j].y : g2[j].x;
#pragma unroll
            for (int j = 0; j < GG; j++) s1[j] += g[j];
            int p = 0;
#pragma unroll
            for (int j = 0; j < GG; j++) {
#pragma unroll
                for (int k = j; k < GG; k++) { s2[p] = fmaf(g[j], g[k], s2[p]); p++; }
            }
        }
    }

    float* dst = g_stats[n][chunk];
#pragma unroll
    for (int q = 0; q < NSTAT; q++) {
        float v = (q < GG) ? s1[q] : s2[q - GG];
#pragma unroll
        for (int o = 16; o > 0; o >>= 1) v += __shfl_xor_sync(FULLMASK, v, o);
        if (lane == (q & 31)) dst[q] = v;
    }
}

// ---------------------------------------------------------------------------
// Kernel B: analytic BN fold, ONE WARP PER RULE (lane a owns column a).
// Covariance lives in shared memory; each lane keeps only its C-row in regs.
// block = 128 (4 warps = 4 rules), grid = NRULES/4.
// ---------------------------------------------------------------------------
__global__ __launch_bounds__(128) void fold_kernel(const int* __restrict__ idx,
                                                   const float* __restrict__ W1,
                                                   const float* __restrict__ bn1_w,
                                                   const float* __restrict__ W2,
                                                   const float* __restrict__ fc2_w) {
    __shared__ float sS[4][NSTAT];       // chunk-summed moments
    __shared__ float sC[4][GG][GG + 1];  // covariance (+1 pad: conflict-free col reads)

    const int w    = threadIdx.x >> 5;                 // warp in block
    const int lane = threadIdx.x & 31;
    const int a    = lane & 15;                        // owned column (dup on hi half)
    const int n    = blockIdx.x * 4 + w;               // rule
    const float invB = 1.0f / (float)BB;

    // 1) sum the 8 chunk partials into shared
    for (int q = lane; q < NSTAT; q += 32) {
        float acc = 0.0f;
#pragma unroll
        for (int c = 0; c < CHUNKS; c++) acc += g_stats[n][c][q];
        sS[w][q] = acc;
    }
    __syncwarp();

    // 2) covariance into shared (lanes split the 136 pairs)
    {
        int p = 0;
#pragma unroll
        for (int j = 0; j < GG; j++) {
#pragma unroll
            for (int k = j; k < GG; k++) {
                if ((p & 31) == lane) {
                    float c = sS[w][GG + p] * invB
                            - (sS[w][j] * invB) * (sS[w][k] * invB);
                    sC[w][j][k] = c;
                    sC[w][k][j] = c;
                }
                p++;
            }
        }
    }
    __syncwarp();

    // 3) lane a caches its row of C
    float Crow[GG];
#pragma unroll
    for (int b = 0; b < GG; b++) Crow[b] = sC[w][a][b];

    const float mu_a = sS[w][a] * invB;
    const float* W1n = W1 + (size_t)n * GG * GG;

    // 4) alpha = sum_j (W2_j * bn1w_j / sigma_hj) * W1[j,:]
    float alpha_a = 0.0f;
#pragma unroll 1
    for (int j = 0; j < GG; j++) {
        float wa = W1n[j * GG + a];                    // lane a holds w[a]
        float t = 0.0f;
#pragma unroll
        for (int b = 0; b < GG; b++)
            t = fmaf(Crow[b], __shfl_sync(FULLMASK, wa, b), t);
        float v = wa * t;                              // varh = w^T C w
#pragma unroll
        for (int o = 8; o > 0; o >>= 1) v += __shfl_xor_sync(FULLMASK, v, o);
        float aj  = bn1_w[n * GG + j] * rsqrtf(v + EPSV);
        float caj = W2[n * GG + j] * aj;
        alpha_a = fmaf(caj, wa, alpha_a);
    }

    // 5) varo = alpha^T C alpha ; muoa = alpha . mu
    float t = 0.0f;
#pragma unroll
    for (int b = 0; b < GG; b++)
        t = fmaf(Crow[b], __shfl_sync(FULLMASK, alpha_a, b), t);
    float varo = alpha_a * t;
    float muoa = alpha_a * mu_a;
#pragma unroll
    for (int o = 8; o > 0; o >>= 1) {
        varo += __shfl_xor_sync(FULLMASK, varo, o);
        muoa += __shfl_xor_sync(FULLMASK, muoa, o);
    }
    float sc = fc2_w[n] * rsqrtf(varo + EPSV);

    // 6) scatter gamma into wF (lanes 0..15 only; hi half is duplicate)
    if (lane < GG) atomicAdd(&g_wF[idx[n * GG + lane]], sc * alpha_a);
    if (lane == 0) atomicAdd(&g_c0, -sc * muoa);
}

// ---------------------------------------------------------------------------
// Kernel C: out[b] = x[b,:] . wF + c0   (8192x2048 GEMV)
// ---------------------------------------------------------------------------
__global__ __launch_bounds__(256) void gemv_kernel(const float* __restrict__ x,
                                                   float* __restrict__ out) {
    const int warp = threadIdx.x >> 5;
    const int lane = threadIdx.x & 31;
    const int row  = blockIdx.x * 8 + warp;

    const float4* xr = reinterpret_cast<const float4*>(x + (size_t)row * FF);
    const float4* wv = reinterpret_cast<const float4*>(g_wF);

    float acc = 0.0f;
#pragma unroll
    for (int i = 0; i < 16; i++) {
        float4 a = __ldg(xr + lane + 32 * i);
        float4 w = wv[lane + 32 * i];
        acc = fmaf(a.x, w.x, acc);
        acc = fmaf(a.y, w.y, acc);
        acc = fmaf(a.z, w.z, acc);
        acc = fmaf(a.w, w.w, acc);
    }
#pragma unroll
    for (int o = 16; o > 0; o >>= 1) acc += __shfl_xor_sync(FULLMASK, acc, o);
    if (lane == 0) out[row] = acc + g_c0;
}

// ---------------------------------------------------------------------------
extern "C" void kernel_launch(void* const* d_in, const int* in_sizes, int n_in,
                              void* d_out, int out_size) {
    const float* x     = (const float*)d_in[0];
    const int*   idx   = (const int*)  d_in[1];
    const float* W1    = (const float*)d_in[2];
    // d_in[3] = b1, d_in[5] = bn1_b, d_in[7] = b2 : cancel exactly under BN
    const float* bn1_w = (const float*)d_in[4];
    const float* W2    = (const float*)d_in[6];
    const float* fc2_w = (const float*)d_in[8];
    const float* fc2_b = (const float*)d_in[9];
    float* out = (float*)d_out;

    zero_kernel<<<(FF + 255) / 256, 256>>>(fc2_b);

    dim3 tgrid(FF / 32, BB / 32);
    transpose_kernel<<<tgrid, 256>>>(x);

    dim3 sgrid(NRULES, CHUNKS / 4);
    stats_kernel<<<sgrid, 128>>>(idx);

    fold_kernel<<<NRULES / 4, 128>>>(idx, W1, bn1_w, W2, fc2_w);

    gemv_kernel<<<BB / 8, 256>>>(x, out);
}

// round 7
// speedup vs baseline: 2.6254x; 1.0160x over previous
#include <cuda_runtime.h>
#include <cuda_bf16.h>

#define BB      8192
#define FF      2048
#define NRULES  512
#define GG      16
#define NPAIR   136          // upper triangle incl. diagonal of 16x16
#define NSTAT   152          // 16 sums + 136 pair-products
#define CHUNKS  8
#define RPC     (BB / CHUNKS)   // 1024 rows per chunk
#define EPSV    1e-5f
#define FULLMASK 0xffffffffu

// Scratch (device globals: allocation-free per harness rules)
__device__ float g_xT[(size_t)FF * BB];            // 64MB transposed x
__device__ float g_stats[NRULES][CHUNKS][NSTAT];   // ~2.5 MB partial moments
__device__ __align__(16) float g_wF[FF];           // folded GEMV weights
__device__ float g_c0;                             // folded constant

// ---------------------------------------------------------------------------
// packed f32x2 helpers (sm_103a; ptxas will not auto-fuse these)
// ---------------------------------------------------------------------------
__device__ __forceinline__ unsigned long long fma2(unsigned long long a,
                                                   unsigned long long b,
                                                   unsigned long long c) {
    unsigned long long d;
    asm("fma.rn.f32x2 %0, %1, %2, %3;" : "=l"(d) : "l"(a), "l"(b), "l"(c));
    return d;
}
__device__ __forceinline__ unsigned long long add2(unsigned long long a,
                                                   unsigned long long b) {
    unsigned long long d;
    asm("add.rn.f32x2 %0, %1, %2;" : "=l"(d) : "l"(a), "l"(b));
    return d;
}
__device__ __forceinline__ float pairsum(unsigned long long v) {
    return __uint_as_float((unsigned)(v & 0xffffffffu)) +
           __uint_as_float((unsigned)(v >> 32));
}

// ---------------------------------------------------------------------------
// Kernel Z: zero the scatter targets every launch (graph replays reuse them)
// ---------------------------------------------------------------------------
__global__ void zero_kernel(const float* __restrict__ fc2_b) {
    int t = blockIdx.x * blockDim.x + threadIdx.x;
    if (t < FF) g_wF[t] = 0.0f;
    if (t == 0) g_c0 = fc2_b[0];
}

// ---------------------------------------------------------------------------
// Kernel T: tiled transpose x(B,F) -> g_xT(F,B). 32x32 tiles, 256 threads.
// ---------------------------------------------------------------------------
__global__ __launch_bounds__(256) void transpose_kernel(const float* __restrict__ x) {
    __shared__ float t[32][33];
    const int tx = threadIdx.x & 31;
    const int ty = threadIdx.x >> 5;          // 0..7
    const int col0 = blockIdx.x * 32;         // F dimension
    const int row0 = blockIdx.y * 32;         // B dimension
#pragma unroll
    for (int i = 0; i < 32; i += 8)
        t[ty + i][tx] = x[(size_t)(row0 + ty + i) * FF + col0 + tx];
    __syncthreads();
#pragma unroll
    for (int i = 0; i < 32; i += 8)
        g_xT[(size_t)(col0 + ty + i) * BB + row0 + tx] = t[tx][ty + i];
}

// ---------------------------------------------------------------------------
// Kernel A: per-rule moments with packed f32x2 FMAs.
// block = 64 (2 warps). Warp 0 accumulates pair-set {j<4 || j>=12} (68 pairs),
// warp 1 the complement {4<=j<12} (68 pairs). Both warps read the same float2
// stream; warp 1's loads hit L1 (same SM/block), so L2 traffic stays 256MB.
// The two packed halves are the even/odd rows; summed at the end.
// ---------------------------------------------------------------------------
#define INSET(PH, j) ((PH) == 0 ? ((j) < 4 || (j) >= 12) : ((j) >= 4 && (j) < 12))

template <int PHASE>
__device__ __forceinline__ void stats_body(int n, int chunk, int lane,
                                           const int* __restrict__ idx) {
    const float* colp[GG];
#pragma unroll
    for (int j = 0; j < GG; j++) {
        int c = __ldg(idx + n * GG + j);               // uniform per block
        colp[j] = g_xT + (size_t)c * BB + chunk * RPC;
    }

    unsigned long long s1[8];                          // 8 packed column sums
    unsigned long long s2[68];                         // 68 packed pair sums
#pragma unroll
    for (int i = 0; i < 8; i++) s1[i] = 0ull;
#pragma unroll
    for (int i = 0; i < 68; i++) s2[i] = 0ull;

#pragma unroll 1
    for (int it = 0; it < RPC / 64; it++) {            // 16 iterations
        const int r = it * 64 + lane * 2;              // 2 rows per lane
        unsigned long long g[GG];
#pragma unroll
        for (int j = 0; j < GG; j++)
            g[j] = __ldg(reinterpret_cast<const unsigned long long*>(colp[j] + r));
        {
            int si = 0;
#pragma unroll
            for (int j = 0; j < GG; j++)
                if (INSET(PHASE, j)) { s1[si] = add2(s1[si], g[j]); si++; }
        }
        {
            int ai = 0;
#pragma unroll
            for (int j = 0; j < GG; j++)
                if (INSET(PHASE, j)) {
#pragma unroll
                    for (int k = j; k < GG; k++) {
                        s2[ai] = fma2(g[j], g[k], s2[ai]);
                        ai++;
                    }
                }
        }
    }

    // reduce packed halves + warp tree, store this warp's subset of q indices
    float* dst = g_stats[n][chunk];
    {
        int si = 0;
#pragma unroll
        for (int j = 0; j < GG; j++)
            if (INSET(PHASE, j)) {
                float v = pairsum(s1[si]); si++;
#pragma unroll
                for (int o = 16; o > 0; o >>= 1) v += __shfl_xor_sync(FULLMASK, v, o);
                if (lane == (j & 31)) dst[j] = v;
            }
    }
    {
        int ai = 0;
#pragma unroll
        for (int j = 0; j < GG; j++)
            if (INSET(PHASE, j)) {
#pragma unroll
                for (int k = j; k < GG; k++) {
                    float v = pairsum(s2[ai]); ai++;
                    const int q = GG + j * GG - j * (j - 1) / 2 + (k - j);
#pragma unroll
                    for (int o = 16; o > 0; o >>= 1) v += __shfl_xor_sync(FULLMASK, v, o);
                    if (lane == (q & 31)) dst[q] = v;
                }
            }
    }
}

__global__ __launch_bounds__(64) void stats_kernel(const int* __restrict__ idx) {
    const int n     = blockIdx.x;
    const int chunk = blockIdx.y;
    const int lane  = threadIdx.x & 31;
    if (threadIdx.x < 32) stats_body<0>(n, chunk, lane, idx);
    else                  stats_body<1>(n, chunk, lane, idx);
}

// ---------------------------------------------------------------------------
// Kernel B: analytic BN fold, one warp per rule, ALL operands staged in SMEM
// before the compute loop (no global loads on the critical path).
// block = 128 (4 warps = 4 rules), grid = NRULES/4.
// ---------------------------------------------------------------------------
__global__ __launch_bounds__(128) void fold_kernel(const int* __restrict__ idx,
                                                   const float* __restrict__ W1,
                                                   const float* __restrict__ bn1_w,
                                                   const float* __restrict__ W2,
                                                   const float* __restrict__ fc2_w) {
    __shared__ float sS[4][NSTAT];       // chunk-summed moments
    __shared__ float sC[4][GG][GG + 1];  // covariance (+1 pad)
    __shared__ float sW[4][GG][GG + 1];  // W1 rows (+1 pad)
    __shared__ float sCB[4][GG];         // W2[j]*bn1_w[j]

    const int w    = threadIdx.x >> 5;
    const int lane = threadIdx.x & 31;
    const int a    = lane & 15;                        // owned column (dup on hi half)
    const int n    = blockIdx.x * 4 + w;
    const float invB = 1.0f / (float)BB;

    // --- batched prefetch: W1 tile, combined scale, moment sums ---
    const float4* w4 = reinterpret_cast<const float4*>(W1 + (size_t)n * GG * GG);
#pragma unroll
    for (int i = lane; i < 64; i += 32) {
        float4 v = __ldg(w4 + i);
        int row = i >> 2, c = (i & 3) * 4;
        sW[w][row][c]     = v.x;
        sW[w][row][c + 1] = v.y;
        sW[w][row][c + 2] = v.z;
        sW[w][row][c + 3] = v.w;
    }
    if (lane < GG)
        sCB[w][lane] = __ldg(W2 + n * GG + lane) * __ldg(bn1_w + n * GG + lane);

    for (int q = lane; q < NSTAT; q += 32) {
        float acc = 0.0f;
#pragma unroll
        for (int c = 0; c < CHUNKS; c++) acc += g_stats[n][c][q];
        sS[w][q] = acc;
    }
    __syncwarp();

    // --- covariance into shared (lanes split the 136 pairs) ---
    {
        int p = 0;
#pragma unroll
        for (int j = 0; j < GG; j++) {
#pragma unroll
            for (int k = j; k < GG; k++) {
                if ((p & 31) == lane) {
                    float c = sS[w][GG + p] * invB
                            - (sS[w][j] * invB) * (sS[w][k] * invB);
                    sC[w][j][k] = c;
                    sC[w][k][j] = c;
                }
                p++;
            }
        }
    }
    __syncwarp();

    float Crow[GG];
#pragma unroll
    for (int b = 0; b < GG; b++) Crow[b] = sC[w][a][b];
    const float mu_a = sS[w][a] * invB;

    // --- alpha = sum_j (W2_j*bn1w_j/sigma_hj) * W1[j,:]  (pure smem/compute) ---
    float alpha_a = 0.0f;
#pragma unroll
    for (int j = 0; j < GG; j++) {
        float t = 0.0f;
#pragma unroll
        for (int b = 0; b < GG; b++) t = fmaf(Crow[b], sW[w][j][b], t);  // LDS broadcast
        float wa = sW[w][j][a];
        float v = wa * t;                              // varh = w^T C w
#pragma unroll
        for (int o = 8; o > 0; o >>= 1) v += __shfl_xor_sync(FULLMASK, v, o);
        float aj = sCB[w][j] * rsqrtf(v + EPSV);
        alpha_a = fmaf(aj, wa, alpha_a);
    }

    // --- varo = alpha^T C alpha ; muoa = alpha . mu ---
    float t = 0.0f;
#pragma unroll
    for (int b = 0; b < GG; b++)
        t = fmaf(Crow[b], __shfl_sync(FULLMASK, alpha_a, b), t);
    float varo = alpha_a * t;
    float muoa = alpha_a * mu_a;
#pragma unroll
    for (int o = 8; o > 0; o >>= 1) {
        varo += __shfl_xor_sync(FULLMASK, varo, o);
        muoa += __shfl_xor_sync(FULLMASK, muoa, o);
    }
    float sc = __ldg(fc2_w + n) * rsqrtf(varo + EPSV);

    if (lane < GG) atomicAdd(&g_wF[__ldg(idx + n * GG + lane)], sc * alpha_a);
    if (lane == 0) atomicAdd(&g_c0, -sc * muoa);
}

// ---------------------------------------------------------------------------
// Kernel C: out[b] = x[b,:] . wF + c0   (8192x2048 GEMV)
// ---------------------------------------------------------------------------
__global__ __launch_bounds__(256) void gemv_kernel(const float* __restrict__ x,
                                                   float* __restrict__ out) {
    const int warp = threadIdx.x >> 5;
    const int lane = threadIdx.x & 31;
    const int row  = blockIdx.x * 8 + warp;

    const float4* xr = reinterpret_cast<const float4*>(x + (size_t)row * FF);
    const float4* wv = reinterpret_cast<const float4*>(g_wF);

    float acc = 0.0f;
#pragma unroll
    for (int i = 0; i < 16; i++) {
        float4 a = __ldg(xr + lane + 32 * i);
        float4 w = wv[lane + 32 * i];
        acc = fmaf(a.x, w.x, acc);
        acc = fmaf(a.y, w.y, acc);
        acc = fmaf(a.z, w.z, acc);
        acc = fmaf(a.w, w.w, acc);
    }
#pragma unroll
    for (int o = 16; o > 0; o >>= 1) acc += __shfl_xor_sync(FULLMASK, acc, o);
    if (lane == 0) out[row] = acc + g_c0;
}

// ---------------------------------------------------------------------------
extern "C" void kernel_launch(void* const* d_in, const int* in_sizes, int n_in,
                              void* d_out, int out_size) {
    const float* x     = (const float*)d_in[0];
    const int*   idx   = (const int*)  d_in[1];
    const float* W1    = (const float*)d_in[2];
    // d_in[3] = b1, d_in[5] = bn1_b, d_in[7] = b2 : cancel exactly under BN
    const float* bn1_w = (const float*)d_in[4];
    const float* W2    = (const float*)d_in[6];
    const float* fc2_w = (const float*)d_in[8];
    const float* fc2_b = (const float*)d_in[9];
    float* out = (float*)d_out;

    zero_kernel<<<(FF + 255) / 256, 256>>>(fc2_b);

    dim3 tgrid(FF / 32, BB / 32);
    transpose_kernel<<<tgrid, 256>>>(x);

    dim3 sgrid(NRULES, CHUNKS);
    stats_kernel<<<sgrid, 64>>>(idx);

    fold_kernel<<<NRULES / 4, 128>>>(idx, W1, bn1_w, W2, fc2_w);

    gemv_kernel<<<BB / 8, 256>>>(x, out);
}